// round 16
// baseline (speedup 1.0000x reference)
#include <cuda_runtime.h>
#include <cuda_fp16.h>
#include <cstdint>
#include <math.h>

// ============================================================================
// VectorQuantizer — base-target ISA (mma.sync m16n8k16 FP16-ACC + ldmatrix +
// cp.async).  N = 262144 rows, D = 64, K = 1024 codes.
//   filter key = fp16 dot(xn, cn_k) (+2.0 in fp32 for positive-key packing)
//   exact key  = dot(xn, cn_k) - 0.5||cn_k||^2  (fp64 rescue, ~30% of rows)
//   branch-free packed-key top-3/lane (12 cand/row), smem overlay, 4 CTAs/SM.
// ============================================================================

#define NROWS   262144
#define DIM     64
#define KCODES  1024
#define NQ      16777216
#define TILES   2048
#define THRESH  1.2e-2f

// ---- device scratch ----
__device__ __align__(16) __half  g_bh[KCODES * DIM];   // normalized codebook fp16
__device__ __align__(16) float   g_cnf[KCODES * DIM];  // normalized codebook fp32
__device__ double                g_biasd[KCODES];      // 0.5*||cn||^2 fp64
__device__ float                 g_partials[TILES];

// ---- smem layout (bytes); cand/list/isw/red OVERLAY the dead A buffer ----
#define SM_B     0          // 2 x (128 codes x 144B)   = 36864
#define SM_A     36864      // 128 rows x 144B          = 18432 (dead post-ldm)
#define SM_CAND  36864      //   overlay: 128 x 12 u16  = 3072
#define SM_LIST  39936      //   overlay: 128 ints      = 512
#define SM_ISW   40448      //   overlay: 128 ints      = 512
#define SM_RED   40960      //   overlay: 8 floats      = 32
#define SM_RN    55296      // 128 floats               = 512
#define SM_CNT   55808      // 16
#define SM_TOTAL 55824

// ---- PTX helpers ----
// fp16-accumulator HMMA: D,C are 2 x .f16x2 registers
__device__ __forceinline__ void mma16816h(uint32_t c[2], const uint32_t a[4],
                                          uint32_t b0, uint32_t b1) {
    asm volatile(
        "mma.sync.aligned.m16n8k16.row.col.f16.f16.f16.f16 "
        "{%0,%1}, {%2,%3,%4,%5}, {%6,%7}, {%0,%1};"
        : "+r"(c[0]), "+r"(c[1])
        : "r"(a[0]), "r"(a[1]), "r"(a[2]), "r"(a[3]), "r"(b0), "r"(b1));
}
__device__ __forceinline__ void ldm4(uint32_t addr, uint32_t& r0, uint32_t& r1,
                                     uint32_t& r2, uint32_t& r3) {
    asm volatile("ldmatrix.sync.aligned.m8n8.x4.shared.b16 {%0,%1,%2,%3}, [%4];"
                 : "=r"(r0), "=r"(r1), "=r"(r2), "=r"(r3) : "r"(addr));
}
__device__ __forceinline__ uint32_t smem_u32(const void* p) {
    uint32_t a;
    asm("{ .reg .u64 t; cvta.to.shared.u64 t, %1; cvt.u32.u64 %0, t; }"
        : "=r"(a) : "l"(p));
    return a;
}
__device__ __forceinline__ void cp16(uint32_t dst, const void* src) {
    asm volatile("cp.async.cg.shared.global [%0], [%1], 16;"
                 :: "r"(dst), "l"(src) : "memory");
}
__device__ __forceinline__ void cp_commit() {
    asm volatile("cp.async.commit_group;" ::: "memory");
}
__device__ __forceinline__ void cp_wait1() {
    asm volatile("cp.async.wait_group 1;" ::: "memory");
}
__device__ __forceinline__ void cp_wait0() {
    asm volatile("cp.async.wait_group 0;" ::: "memory");
}

// packed key: upper 22 bits = (2.0 + score) bits, low 10 bits = (1023 - col)
__device__ __forceinline__ uint32_t pkkey(float s, uint32_t invk) {
    return (__float_as_uint(s) & 0xFFFFFC00u) | invk;
}
// branch-free sorted top-3 insert: K0 >= K1 >= K2 (5 min/max ops)
__device__ __forceinline__ void ins3u(uint32_t K[3], uint32_t s) {
    uint32_t l0 = umin(s, K[0]);  K[0] = umax(s, K[0]);
    uint32_t l1 = umin(l0, K[1]); K[1] = umax(l0, K[1]);
    K[2] = umax(l1, K[2]);
}

// ============================================================================
// Kernel 1: codebook prep — warp per code
// ============================================================================
__global__ void vq_prep(const float* __restrict__ cb) {
    int wid  = threadIdx.x >> 5;
    int lane = threadIdx.x & 31;
    int k = blockIdx.x * 8 + wid;
    float2 v = ((const float2*)(cb + (size_t)k * DIM))[lane];
    float s = v.x * v.x + v.y * v.y;
    #pragma unroll
    for (int o = 16; o > 0; o >>= 1) s += __shfl_xor_sync(0xffffffffu, s, o);
    float n = fmaxf(sqrtf(s), 1e-12f);
    float a0 = v.x / n, a1 = v.y / n;
    ((float2*)(g_cnf + (size_t)k * DIM))[lane] = make_float2(a0, a1);
    ((__half2*)(g_bh + (size_t)k * DIM))[lane] =
        __halves2half2(__float2half_rn(a0), __float2half_rn(a1));
    double bd = (double)a0 * (double)a0 + (double)a1 * (double)a1;
    #pragma unroll
    for (int o = 16; o > 0; o >>= 1) bd += __shfl_xor_sync(0xffffffffu, bd, o);
    if (lane == 0) g_biasd[k] = 0.5 * bd;
}

// ============================================================================
// Kernel 2: GEMM + argmax + rescue + outputs. 128 rows/CTA, 8 warps x m16.
// ============================================================================
__global__ void __launch_bounds__(256, 4)
vq_main(const float* __restrict__ x, const float* __restrict__ cb,
        float* __restrict__ out) {
    extern __shared__ char smem[];
    const uint32_t sb = smem_u32(smem);
    const int tid  = threadIdx.x;
    const int wid  = tid >> 5;
    const int lane = tid & 31;
    const int row0 = blockIdx.x * 128;

    float*    rnsm = (float*)(smem + SM_RN);
    uint16_t* cand = (uint16_t*)(smem + SM_CAND);
    int*      list = (int*)(smem + SM_LIST);
    int*      cnt  = (int*)(smem + SM_CNT);
    int*      isw  = (int*)(smem + SM_ISW);
    float*    red  = (float*)(smem + SM_RED);

    if (tid == 0) *cnt = 0;

    // ---- prefetch B chunks 0,1 via cp.async ----
    const __half* bh = g_bh;
    #pragma unroll
    for (int pc = 0; pc < 2; pc++) {
        #pragma unroll
        for (int i = 0; i < 4; i++) {
            int idx = tid + i * 256;          // 0..1023
            int r = idx >> 3, seg = idx & 7;
            cp16(sb + SM_B + pc * 18432 + r * 144 + seg * 16,
                 bh + ((size_t)(pc * 128 + r)) * DIM + seg * 8);
        }
        cp_commit();
    }

    // ---- normalize rows -> fp16 A (warp per row, gmem-direct) ----
    {
        const float2* x2 = (const float2*)(x + (size_t)row0 * DIM);
        #pragma unroll 4
        for (int j = 0; j < 16; j++) {
            int r = wid + 8 * j;              // 0..127
            float2 v = x2[r * 32 + lane];
            float s = v.x * v.x + v.y * v.y;
            #pragma unroll
            for (int o = 16; o > 0; o >>= 1)
                s += __shfl_xor_sync(0xffffffffu, s, o);
            float n = fmaxf(sqrtf(s), 1e-12f);
            if (lane == 0) rnsm[r] = n;
            *(__half2*)(smem + SM_A + r * 144 + lane * 4) =
                __halves2half2(__float2half_rn(v.x / n), __float2half_rn(v.y / n));
        }
    }
    __syncthreads();

    // ---- A fragments via ldmatrix (persist in registers) ----
    const int lr = lane & 7, m = lane >> 3;
    const int Rb = wid * 16;
    const uint32_t a_loff = (uint32_t)((lr + (m & 1) * 8) * 144 + (m >> 1) * 16);
    const uint32_t b_loff = (uint32_t)(((m >> 1) * 8 + lr) * 144 + (m & 1) * 16);
    uint32_t afr[4][4];
    #pragma unroll
    for (int ks = 0; ks < 4; ks++)
        ldm4(sb + SM_A + (uint32_t)(Rb * 144 + ks * 32) + a_loff,
             afr[ks][0], afr[ks][1], afr[ks][2], afr[ks][3]);
    __syncthreads();                           // A buffer now dead (overlay ok)

    // ---- main loop: 8 chunks of 128 codes, double-buffered ----
    uint32_t K0[3] = {0, 0, 0}, K1[3] = {0, 0, 0};
    const int c = lane & 3;

    #pragma unroll 1
    for (int ch = 0; ch < 8; ch++) {
        if (ch == 7) cp_wait0(); else cp_wait1();
        __syncthreads();
        const uint32_t Bb = sb + SM_B + (uint32_t)((ch & 1) * 18432) + b_loff;
        const int cb0 = ch * 128 + 2 * c;

        #pragma unroll
        for (int nbp = 0; nbp < 8; nbp++) {
            uint32_t a0[2] = {0u, 0u};         // fp16x2 accumulators
            uint32_t a1[2] = {0u, 0u};
            #pragma unroll
            for (int ks = 0; ks < 4; ks++) {
                uint32_t b0, b1, b2, b3;
                ldm4(Bb + (uint32_t)(nbp * 2304 + ks * 32), b0, b1, b2, b3);
                mma16816h(a0, afr[ks], b0, b1);
                mma16816h(a1, afr[ks], b2, b3);
            }
            // epilogue: cvt fp16->fp32, +2.0, packed key, top-3
            int col0 = cb0 + nbp * 16;
            uint32_t inv = (uint32_t)(1023 - col0);
            float2 f00 = __half22float2(*(__half2*)&a0[0]);  // row g,   cols 2c,2c+1
            float2 f01 = __half22float2(*(__half2*)&a0[1]);  // row g+8
            float2 f10 = __half22float2(*(__half2*)&a1[0]);  // row g,   cols +8
            float2 f11 = __half22float2(*(__half2*)&a1[1]);  // row g+8
            ins3u(K0, pkkey(2.0f + f00.x, inv));
            ins3u(K0, pkkey(2.0f + f00.y, inv - 1));
            ins3u(K0, pkkey(2.0f + f10.x, inv - 8));
            ins3u(K0, pkkey(2.0f + f10.y, inv - 9));
            ins3u(K1, pkkey(2.0f + f01.x, inv));
            ins3u(K1, pkkey(2.0f + f01.y, inv - 1));
            ins3u(K1, pkkey(2.0f + f11.x, inv - 8));
            ins3u(K1, pkkey(2.0f + f11.y, inv - 9));
        }
        __syncthreads();
        if (ch < 6) {                          // prefetch chunk ch+2
            int pc = ch + 2;
            #pragma unroll
            for (int i = 0; i < 4; i++) {
                int idx = tid + i * 256;
                int r = idx >> 3, seg = idx & 7;
                cp16(sb + SM_B + (pc & 1) * 18432 + r * 144 + seg * 16,
                     bh + ((size_t)(pc * 128 + r)) * DIM + seg * 8);
            }
            cp_commit();
        }
    }

    // ---- quad merge: row best / margin / candidate dump ----
    const int g = lane >> 2;
    #pragma unroll
    for (int h = 0; h < 2; h++) {
        uint32_t* K = h ? K1 : K0;
        int row = Rb + 8 * h + g;
        uint32_t bs = K[0];
        bs = umax(bs, __shfl_xor_sync(0xffffffffu, bs, 1));
        bs = umax(bs, __shfl_xor_sync(0xffffffffu, bs, 2));
        uint32_t sc = (K[0] == bs) ? K[1] : K[0];
        sc = umax(sc, __shfl_xor_sync(0xffffffffu, sc, 1));
        sc = umax(sc, __shfl_xor_sync(0xffffffffu, sc, 2));
        #pragma unroll
        for (int j = 0; j < 3; j++)
            cand[row * 12 + 3 * c + j] = (uint16_t)(1023u - (K[j] & 1023u));
        if (c == 0) {
            isw[row] = (int)(1023u - (bs & 1023u));
            float mf = __uint_as_float(bs & 0xFFFFFC00u)
                     - __uint_as_float(sc & 0xFFFFFC00u);
            if (mf < THRESH) { int p = atomicAdd(cnt, 1); list[p] = row; }
        }
    }
    __syncthreads();

    // ---- fp64 rescue of tight rows (12 candidates each, warp per row) ----
    int nflag = *cnt;
    for (int e = wid; e < nflag; e += 8) {
        int row = list[e];
        double scv = -1e300; int kk = 0x7fffffff;
        if (lane < 12) {
            kk = (int)cand[row * 12 + lane];
            float rn = rnsm[row];
            const float* cp = g_cnf + (size_t)kk * DIM;
            const float* xr = x + (size_t)(row0 + row) * DIM;
            double d0 = 0, d1 = 0, d2 = 0, d3 = 0;
            #pragma unroll
            for (int j = 0; j < DIM; j += 4) {
                d0 += (double)(xr[j]     / rn) * (double)cp[j];
                d1 += (double)(xr[j + 1] / rn) * (double)cp[j + 1];
                d2 += (double)(xr[j + 2] / rn) * (double)cp[j + 2];
                d3 += (double)(xr[j + 3] / rn) * (double)cp[j + 3];
            }
            scv = ((d0 + d1) + (d2 + d3)) - g_biasd[kk];
        }
        #pragma unroll
        for (int off = 1; off <= 8; off <<= 1) {
            double os = __shfl_xor_sync(0xffffffffu, scv, off);
            int    oi = __shfl_xor_sync(0xffffffffu, kk, off);
            if (os > scv || (os == scv && oi < kk)) { scv = os; kk = oi; }
        }
        if (lane == 0) isw[row] = kk;
    }
    __syncthreads();

    // ---- outputs: STE quantized + indices + partial SSE ----
    const float4* xg4 = (const float4*)(x + (size_t)row0 * DIM);
    float4*       og4 = (float4*)(out + (size_t)row0 * DIM);
    float sse = 0.f;
    #pragma unroll
    for (int i = 0; i < 8; i++) {
        int e4 = tid + i * 256;                // 0..2047 float4
        int r = e4 >> 4, c4 = e4 & 15;
        int k = isw[r];
        float4 xv = xg4[e4];
        float4 q  = *(const float4*)(cb + (size_t)k * DIM + c4 * 4);
        float4 o; float d;
        d = q.x - xv.x; sse += d * d; o.x = xv.x + d;
        d = q.y - xv.y; sse += d * d; o.y = xv.y + d;
        d = q.z - xv.z; sse += d * d; o.z = xv.z + d;
        d = q.w - xv.w; sse += d * d; o.w = xv.w + d;
        og4[e4] = o;
    }
    if (tid < 128) out[(size_t)NQ + 2 + row0 + tid] = (float)isw[tid];

    #pragma unroll
    for (int o = 16; o > 0; o >>= 1) sse += __shfl_xor_sync(0xffffffffu, sse, o);
    if (lane == 0) red[wid] = sse;
    __syncthreads();
    if (tid == 0) {
        float t = 0.f;
        #pragma unroll
        for (int w = 0; w < 8; w++) t += red[w];
        g_partials[blockIdx.x] = t;
    }
}

// ============================================================================
// Kernel 3: reduce partials -> both losses
// ============================================================================
__global__ void vq_fin(float* __restrict__ out) {
    __shared__ float red[8];
    int tid = threadIdx.x;
    float s = 0.f;
    #pragma unroll
    for (int i = 0; i < 8; i++) s += g_partials[tid + i * 256];
    #pragma unroll
    for (int o = 16; o > 0; o >>= 1) s += __shfl_xor_sync(0xffffffffu, s, o);
    if ((tid & 31) == 0) red[tid >> 5] = s;
    __syncthreads();
    if (tid == 0) {
        float t = 0.f;
        #pragma unroll
        for (int w = 0; w < 8; w++) t += red[w];
        float loss = t / 16777216.0f;
        out[NQ]     = loss;   // codebook_loss
        out[NQ + 1] = loss;   // commitment_loss
    }
}

// ============================================================================
extern "C" void kernel_launch(void* const* d_in, const int* in_sizes, int n_in,
                              void* d_out, int out_size) {
    const float* x;
    const float* cb;
    if (in_sizes[0] == NROWS * DIM) {
        x  = (const float*)d_in[0];
        cb = (const float*)d_in[1];
    } else {
        x  = (const float*)d_in[1];
        cb = (const float*)d_in[0];
    }
    float* out = (float*)d_out;

    cudaFuncSetAttribute(vq_main, cudaFuncAttributeMaxDynamicSharedMemorySize, SM_TOTAL);

    vq_prep<<<128, 256>>>(cb);
    vq_main<<<TILES, 256, SM_TOTAL>>>(x, cb, out);
    vq_fin<<<1, 256>>>(out);
}

// round 17
// speedup vs baseline: 3.6933x; 3.6933x over previous
#include <cuda_runtime.h>
#include <cuda_fp16.h>
#include <cstdint>
#include <math.h>

// ============================================================================
// VectorQuantizer — base-target ISA (mma.sync m16n8k16 f32acc + ldmatrix +
// cp.async).  N = 262144 rows, D = 64, K = 1024 codes.
//   filter key = dot(xn, cn_k) + 2.0  (||cn||=1: bias const to 5e-8; exact
//                per-k bias kept in the fp64 rescue)
//   R17: XOR-swizzled 128B-stride B, 3-stage ring w/ single sync per chunk,
//        last-CTA loss reduction (no vq_fin launch), 4 CTAs/SM.
// ============================================================================

#define NROWS   262144
#define DIM     64
#define KCODES  1024
#define NQ      16777216
#define TILES   2048
#define THRESH  2e-3f

// ---- device scratch ----
__device__ __align__(16) __half  g_bh[KCODES * DIM];   // normalized codebook fp16
__device__ __align__(16) float   g_cnf[KCODES * DIM];  // normalized codebook fp32
__device__ double                g_biasd[KCODES];      // 0.5*||cn||^2 fp64
__device__ float                 g_partials[TILES];
__device__ unsigned int          g_done = 0;           // last-CTA counter

// ---- smem layout (bytes) ----
// B ring: 3 x (128 codes x 128B, XOR-swizzled) = 49152.
// A (128 x 128B swizzled) staged in buf2; dead after fragment load.
#define SM_B     0
#define SM_CAND  49152      // 128 x 8 u16  = 2048
#define SM_LIST  51200      // 128 ints     = 512
#define SM_ISW   51712      // 128 ints     = 512
#define SM_RN    52224      // 128 floats   = 512
#define SM_RED   52736      // 8 floats     = 32
#define SM_CNT   52768      // 16
#define SM_TOTAL 52784

// ---- PTX helpers ----
__device__ __forceinline__ void mma16816(float c[4], const uint32_t a[4],
                                         uint32_t b0, uint32_t b1) {
    asm volatile(
        "mma.sync.aligned.m16n8k16.row.col.f32.f16.f16.f32 "
        "{%0,%1,%2,%3}, {%4,%5,%6,%7}, {%8,%9}, {%0,%1,%2,%3};"
        : "+f"(c[0]), "+f"(c[1]), "+f"(c[2]), "+f"(c[3])
        : "r"(a[0]), "r"(a[1]), "r"(a[2]), "r"(a[3]), "r"(b0), "r"(b1));
}
__device__ __forceinline__ void ldm4(uint32_t addr, uint32_t& r0, uint32_t& r1,
                                     uint32_t& r2, uint32_t& r3) {
    asm volatile("ldmatrix.sync.aligned.m8n8.x4.shared.b16 {%0,%1,%2,%3}, [%4];"
                 : "=r"(r0), "=r"(r1), "=r"(r2), "=r"(r3) : "r"(addr));
}
__device__ __forceinline__ uint32_t smem_u32(const void* p) {
    uint32_t a;
    asm("{ .reg .u64 t; cvta.to.shared.u64 t, %1; cvt.u32.u64 %0, t; }"
        : "=r"(a) : "l"(p));
    return a;
}
__device__ __forceinline__ void cp16(uint32_t dst, const void* src) {
    asm volatile("cp.async.cg.shared.global [%0], [%1], 16;"
                 :: "r"(dst), "l"(src) : "memory");
}
__device__ __forceinline__ void cp_commit() {
    asm volatile("cp.async.commit_group;" ::: "memory");
}
__device__ __forceinline__ void cp_wait2() {
    asm volatile("cp.async.wait_group 2;" ::: "memory");
}
__device__ __forceinline__ void cp_wait1() {
    asm volatile("cp.async.wait_group 1;" ::: "memory");
}
__device__ __forceinline__ void cp_wait0() {
    asm volatile("cp.async.wait_group 0;" ::: "memory");
}

// packed key: upper 22 bits = (2.0 + score) bits, low 10 bits = (1023 - col)
__device__ __forceinline__ uint32_t pkkey(float s, uint32_t invk) {
    return (__float_as_uint(s) & 0xFFFFFC00u) | invk;
}
// branch-free sorted top-2 insert: K0 >= K1
__device__ __forceinline__ void ins2u(uint32_t K[2], uint32_t s) {
    uint32_t lo = umin(s, K[0]);
    K[0] = umax(s, K[0]);
    K[1] = umax(lo, K[1]);
}

// ============================================================================
// Kernel 1: codebook prep — warp per code
// ============================================================================
__global__ void vq_prep(const float* __restrict__ cb) {
    int wid  = threadIdx.x >> 5;
    int lane = threadIdx.x & 31;
    int k = blockIdx.x * 8 + wid;
    float2 v = ((const float2*)(cb + (size_t)k * DIM))[lane];
    float s = v.x * v.x + v.y * v.y;
    #pragma unroll
    for (int o = 16; o > 0; o >>= 1) s += __shfl_xor_sync(0xffffffffu, s, o);
    float n = fmaxf(sqrtf(s), 1e-12f);
    float a0 = v.x / n, a1 = v.y / n;
    ((float2*)(g_cnf + (size_t)k * DIM))[lane] = make_float2(a0, a1);
    ((__half2*)(g_bh + (size_t)k * DIM))[lane] =
        __halves2half2(__float2half_rn(a0), __float2half_rn(a1));
    double bd = (double)a0 * (double)a0 + (double)a1 * (double)a1;
    #pragma unroll
    for (int o = 16; o > 0; o >>= 1) bd += __shfl_xor_sync(0xffffffffu, bd, o);
    if (lane == 0) g_biasd[k] = 0.5 * bd;
}

// ============================================================================
// Kernel 2: GEMM + argmax + rescue + outputs (+ last-CTA loss reduction)
// ============================================================================
__global__ void __launch_bounds__(256, 4)
vq_main(const float* __restrict__ x, const float* __restrict__ cb,
        float* __restrict__ out) {
    extern __shared__ char smem[];
    const uint32_t sb = smem_u32(smem);
    const int tid  = threadIdx.x;
    const int wid  = tid >> 5;
    const int lane = tid & 31;
    const int row0 = blockIdx.x * 128;

    float*    rnsm = (float*)(smem + SM_RN);
    uint16_t* cand = (uint16_t*)(smem + SM_CAND);
    int*      list = (int*)(smem + SM_LIST);
    int*      cnt  = (int*)(smem + SM_CNT);
    int*      isw  = (int*)(smem + SM_ISW);
    float*    red  = (float*)(smem + SM_RED);

    if (tid == 0) *cnt = 0;

    // ---- prefetch B chunks 0,1 into ring buffers 0,1 (swizzled) ----
    const __half* bh = g_bh;
    #pragma unroll
    for (int pc = 0; pc < 2; pc++) {
        #pragma unroll
        for (int i = 0; i < 4; i++) {
            int idx = tid + i * 256;          // 0..1023 = (row, seg)
            int r = idx >> 3, s = idx & 7;
            uint32_t dst = sb + SM_B + (uint32_t)(pc * 16384)
                         + (uint32_t)(r * 128) + (uint32_t)(((s ^ (r & 7)) * 16));
            cp16(dst, bh + ((size_t)(pc * 128 + r)) * DIM + s * 8);
        }
        cp_commit();
    }

    // ---- normalize rows -> fp16 A, staged (swizzled) in ring buffer 2 ----
    {
        const float2* x2 = (const float2*)(x + (size_t)row0 * DIM);
        const uint32_t Abase = sb + SM_B + 32768;
        #pragma unroll 4
        for (int j = 0; j < 16; j++) {
            int r = wid + 8 * j;              // 0..127
            float2 v = x2[r * 32 + lane];
            float s = v.x * v.x + v.y * v.y;
            #pragma unroll
            for (int o = 16; o > 0; o >>= 1)
                s += __shfl_xor_sync(0xffffffffu, s, o);
            float n = fmaxf(sqrtf(s), 1e-12f);
            if (lane == 0) rnsm[r] = n;
            uint32_t aoff = (uint32_t)(r * 128)
                          + (uint32_t)((((lane >> 2) ^ (r & 7)) * 16))
                          + (uint32_t)((lane & 3) * 4);
            *(__half2*)((char*)smem + (Abase - sb) + aoff) =
                __halves2half2(__float2half_rn(v.x / n), __float2half_rn(v.y / n));
        }
    }
    __syncthreads();

    // ---- A fragments via ldmatrix (swizzled addressing) ----
    const int lr = lane & 7, m = lane >> 3;
    const int Rb = wid * 16;
    uint32_t afr[4][4];
    {
        const uint32_t Abase = sb + SM_B + 32768;
        int arow = Rb + lr + (m & 1) * 8;     // arow & 7 == lr
        #pragma unroll
        for (int ks = 0; ks < 4; ks++) {
            uint32_t aaddr = Abase + (uint32_t)(arow * 128)
                           + (uint32_t)((((ks * 2 + (m >> 1)) ^ lr) * 16));
            ldm4(aaddr, afr[ks][0], afr[ks][1], afr[ks][2], afr[ks][3]);
        }
    }

    // B fragment lane offsets per k-slice (row & 7 == lr)
    uint32_t bloff[4];
    #pragma unroll
    for (int ks = 0; ks < 4; ks++)
        bloff[ks] = (uint32_t)((((m >> 1) * 8 + lr) * 128))
                  + (uint32_t)((((ks * 2 + (m & 1)) ^ lr) * 16));

    // ---- main loop: 8 chunks, 3-stage ring, ONE sync per chunk ----
    uint32_t K0[2] = {0, 0}, K1[2] = {0, 0};
    const int c = lane & 3;
    int bsel = 0;                              // ch % 3
    int psel = 2;                              // (ch+2) % 3

    #pragma unroll 1
    for (int ch = 0; ch < 8; ch++) {
        __syncthreads();                       // all warps done reading buf psel
        if (ch < 6) {                          // prefetch chunk ch+2 -> buf psel
            int pc = ch + 2;
            #pragma unroll
            for (int i = 0; i < 4; i++) {
                int idx = tid + i * 256;
                int r = idx >> 3, s = idx & 7;
                uint32_t dst = sb + SM_B + (uint32_t)(psel * 16384)
                             + (uint32_t)(r * 128)
                             + (uint32_t)(((s ^ (r & 7)) * 16));
                cp16(dst, bh + ((size_t)(pc * 128 + r)) * DIM + s * 8);
            }
            cp_commit();
            cp_wait2();                        // chunk ch has landed
        } else if (ch == 6) {
            cp_wait1();
        } else {
            cp_wait0();
        }
        const uint32_t Bb = sb + SM_B + (uint32_t)(bsel * 16384);
        const int cb0 = ch * 128 + 2 * c;

        #pragma unroll
        for (int nbp = 0; nbp < 8; nbp++) {
            float acc0[4] = {2.0f, 2.0f, 2.0f, 2.0f};
            float acc1[4] = {2.0f, 2.0f, 2.0f, 2.0f};
            #pragma unroll
            for (int ks = 0; ks < 4; ks++) {
                uint32_t b0, b1, b2, b3;
                ldm4(Bb + (uint32_t)(nbp * 2048) + bloff[ks], b0, b1, b2, b3);
                mma16816(acc0, afr[ks], b0, b1);
                mma16816(acc1, afr[ks], b2, b3);
            }
            int col0 = cb0 + nbp * 16;
            uint32_t inv = (uint32_t)(1023 - col0);
            ins2u(K0, pkkey(acc0[0], inv));
            ins2u(K0, pkkey(acc0[1], inv - 1));
            ins2u(K0, pkkey(acc1[0], inv - 8));
            ins2u(K0, pkkey(acc1[1], inv - 9));
            ins2u(K1, pkkey(acc0[2], inv));
            ins2u(K1, pkkey(acc0[3], inv - 1));
            ins2u(K1, pkkey(acc1[2], inv - 8));
            ins2u(K1, pkkey(acc1[3], inv - 9));
        }
        bsel = (bsel == 2) ? 0 : bsel + 1;
        psel = (psel == 2) ? 0 : psel + 1;
    }
    __syncthreads();

    // ---- quad merge: row best / margin / candidate dump ----
    const int g = lane >> 2;
    #pragma unroll
    for (int h = 0; h < 2; h++) {
        uint32_t* K = h ? K1 : K0;
        int row = Rb + 8 * h + g;
        uint32_t bs = K[0];
        bs = umax(bs, __shfl_xor_sync(0xffffffffu, bs, 1));
        bs = umax(bs, __shfl_xor_sync(0xffffffffu, bs, 2));
        uint32_t sc = (K[0] == bs) ? K[1] : K[0];
        sc = umax(sc, __shfl_xor_sync(0xffffffffu, sc, 1));
        sc = umax(sc, __shfl_xor_sync(0xffffffffu, sc, 2));
        cand[row * 8 + 2 * c]     = (uint16_t)(1023u - (K[0] & 1023u));
        cand[row * 8 + 2 * c + 1] = (uint16_t)(1023u - (K[1] & 1023u));
        if (c == 0) {
            isw[row] = (int)(1023u - (bs & 1023u));
            float mf = __uint_as_float(bs & 0xFFFFFC00u)
                     - __uint_as_float(sc & 0xFFFFFC00u);
            if (mf < THRESH) { int p = atomicAdd(cnt, 1); list[p] = row; }
        }
    }
    __syncthreads();

    // ---- fp64 rescue of tight rows (8 candidates each, warp per row) ----
    int nflag = *cnt;
    for (int e = wid; e < nflag; e += 8) {
        int row = list[e];
        double scv = -1e300; int kk = 0x7fffffff;
        if (lane < 8) {
            kk = (int)cand[row * 8 + lane];
            float rn = rnsm[row];
            const float* cp = g_cnf + (size_t)kk * DIM;
            const float* xr = x + (size_t)(row0 + row) * DIM;
            double d0 = 0, d1 = 0, d2 = 0, d3 = 0;
            #pragma unroll
            for (int j = 0; j < DIM; j += 4) {
                d0 += (double)(xr[j]     / rn) * (double)cp[j];
                d1 += (double)(xr[j + 1] / rn) * (double)cp[j + 1];
                d2 += (double)(xr[j + 2] / rn) * (double)cp[j + 2];
                d3 += (double)(xr[j + 3] / rn) * (double)cp[j + 3];
            }
            scv = ((d0 + d1) + (d2 + d3)) - g_biasd[kk];
        }
        #pragma unroll
        for (int off = 1; off <= 8; off <<= 1) {
            double os = __shfl_xor_sync(0xffffffffu, scv, off);
            int    oi = __shfl_xor_sync(0xffffffffu, kk, off);
            if (os > scv || (os == scv && oi < kk)) { scv = os; kk = oi; }
        }
        if (lane == 0) isw[row] = kk;
    }
    __syncthreads();

    // ---- outputs: STE quantized + indices + partial SSE ----
    const float4* xg4 = (const float4*)(x + (size_t)row0 * DIM);
    float4*       og4 = (float4*)(out + (size_t)row0 * DIM);
    float sse = 0.f;
    #pragma unroll
    for (int i = 0; i < 8; i++) {
        int e4 = tid + i * 256;                // 0..2047 float4
        int r = e4 >> 4, c4 = e4 & 15;
        int k = isw[r];
        float4 xv = xg4[e4];
        float4 q  = *(const float4*)(cb + (size_t)k * DIM + c4 * 4);
        float4 o; float d;
        d = q.x - xv.x; sse += d * d; o.x = xv.x + d;
        d = q.y - xv.y; sse += d * d; o.y = xv.y + d;
        d = q.z - xv.z; sse += d * d; o.z = xv.z + d;
        d = q.w - xv.w; sse += d * d; o.w = xv.w + d;
        og4[e4] = o;
    }
    if (tid < 128) out[(size_t)NQ + 2 + row0 + tid] = (float)isw[tid];

    #pragma unroll
    for (int o = 16; o > 0; o >>= 1) sse += __shfl_xor_sync(0xffffffffu, sse, o);
    if (lane == 0) red[wid] = sse;
    __syncthreads();

    // ---- publish partial; last CTA reduces all partials -> losses ----
    if (tid == 0) {
        float t = 0.f;
        #pragma unroll
        for (int w = 0; w < 8; w++) t += red[w];
        g_partials[blockIdx.x] = t;
        __threadfence();
        unsigned int p = atomicAdd(&g_done, 1u);
        *cnt = (p == TILES - 1) ? 1 : 0;
    }
    __syncthreads();
    if (*cnt) {
        __threadfence();
        float s = 0.f;
        #pragma unroll
        for (int i = 0; i < 8; i++) s += g_partials[tid + i * 256];
        #pragma unroll
        for (int o = 16; o > 0; o >>= 1)
            s += __shfl_xor_sync(0xffffffffu, s, o);
        if (lane == 0) red[wid] = s;
        __syncthreads();
        if (tid == 0) {
            float t = 0.f;
            #pragma unroll
            for (int w = 0; w < 8; w++) t += red[w];
            float loss = t / 16777216.0f;
            out[NQ]     = loss;   // codebook_loss
            out[NQ + 1] = loss;   // commitment_loss
            g_done = 0;           // reset for graph replay
        }
    }
}

// ============================================================================
extern "C" void kernel_launch(void* const* d_in, const int* in_sizes, int n_in,
                              void* d_out, int out_size) {
    const float* x;
    const float* cb;
    if (in_sizes[0] == NROWS * DIM) {
        x  = (const float*)d_in[0];
        cb = (const float*)d_in[1];
    } else {
        x  = (const float*)d_in[1];
        cb = (const float*)d_in[0];
    }
    float* out = (float*)d_out;

    cudaFuncSetAttribute(vq_main, cudaFuncAttributeMaxDynamicSharedMemorySize, SM_TOTAL);

    vq_prep<<<128, 256>>>(cb);
    vq_main<<<TILES, 256, SM_TOTAL>>>(x, cb, out);
}